// round 11
// baseline (speedup 1.0000x reference)
#include <cuda_runtime.h>

#define DEGREE   6
#define WIDTH    7           // DEGREE - START_DEGREE + 1
#define FEAT     1024        // in_features
#define OUTF     1024        // out_features
#define THREADS  128
#define NWARPS   4
#define ROWS_PER_BLOCK 2     // 2 warps per row, 16 features per lane
#define GRID     1024        // all resident in ONE wave (~7 blocks/SM)
#define NGROUPS  2048        // 4096 rows / 2; == 2 * GRID exactly
#define CPAD     1032        // padded coeff row stride (banks: 1032%32==8)

__device__ __forceinline__ float ex2f(float x) {
    float r; asm("ex2.approx.f32 %0, %1;" : "=f"(r) : "f"(x)); return r;
}
__device__ __forceinline__ float clipf(float v) {
    return fminf(fmaxf(v, -100.0f), 100.0f);
}

// ---------- phase-1 eval: 16 features -> 7 partial sums (scalar) ----------
__device__ __forceinline__ void eval16(const float4* __restrict__ xv,
                                       float inv_s, float kexp,
                                       float* __restrict__ a)
{
#pragma unroll
    for (int w = 0; w < WIDTH; ++w) a[w] = 0.0f;

#pragma unroll
    for (int i = 0; i < 4; ++i) {
        const float xe[4] = { xv[i].x, xv[i].y, xv[i].z, xv[i].w };
#pragma unroll
        for (int e = 0; e < 4; ++e) {
            const float xq  = xe[e];
            const float txs = xq * (2.0f * inv_s);   // 2*xs = H1
            // g = exp(-xs^2); min(xs^2,50) never binds (delta ~e-50 << tol)
            const float g   = ex2f(xq * xq * kexp);

            a[0] += g;                               // g * H0
            a[1] += g * txs;                         // g * H1

            float hm2 = txs;
            float h   = txs * txs - 2.0f;            // H2: clip can't bind
            a[2] += g * h;                           //  where g > 8e-12
            float hm1 = h;
#pragma unroll
            for (int n = 3; n <= DEGREE; ++n) {
                float t = (-2.0f * (float)(n - 1)) * hm2;  // FMUL-imm
                h = fmaf(txs, hm1, t);
                h = clipf(h);                        // clip BEFORE recursion use
                a[n] += g * h;
                hm2 = hm1;
                hm1 = h;
            }
        }
    }
}

__device__ __forceinline__ void reduce_store(float* __restrict__ a,
                                             float (*s_part)[WIDTH],
                                             int warp, int lane)
{
#pragma unroll
    for (int w = 0; w < WIDTH; ++w) {
#pragma unroll
        for (int off = 16; off > 0; off >>= 1)
            a[w] += __shfl_xor_sync(0xffffffffu, a[w], off);
    }
    if (lane == 0) {
#pragma unroll
        for (int w = 0; w < WIDTH; ++w)
            s_part[warp][w] = a[w];
    }
}

// phase 2: 2 rows x 8 output columns per thread (cols 4t..4t+3 and 512+4t..)
__device__ __forceinline__ void phase2(const float (*s_part)[WIDTH],
                                       const float* __restrict__ s_coef,
                                       float* __restrict__ out,
                                       int group, int tid)
{
    float bs0[WIDTH], bs1[WIDTH];
#pragma unroll
    for (int w = 0; w < WIDTH; ++w) {
        bs0[w] = s_part[0][w] + s_part[1][w];
        bs1[w] = s_part[2][w] + s_part[3][w];
    }
    const int r0 = group * ROWS_PER_BLOCK;

#pragma unroll
    for (int p = 0; p < 2; ++p) {
        const int col = 4 * tid + 512 * p;
        float4 o0 = make_float4(0.f, 0.f, 0.f, 0.f);
        float4 o1 = make_float4(0.f, 0.f, 0.f, 0.f);
#pragma unroll
        for (int w = 0; w < WIDTH; ++w) {
            const float4 cw = *reinterpret_cast<const float4*>(
                s_coef + w * CPAD + col);            // conflict-free LDS.128
            o0.x += bs0[w] * cw.x;  o0.y += bs0[w] * cw.y;
            o0.z += bs0[w] * cw.z;  o0.w += bs0[w] * cw.w;
            o1.x += bs1[w] * cw.x;  o1.y += bs1[w] * cw.y;
            o1.z += bs1[w] * cw.z;  o1.w += bs1[w] * cw.w;
        }
        *reinterpret_cast<float4*>(out + (size_t)r0 * OUTF + col)       = o0;
        *reinterpret_cast<float4*>(out + (size_t)(r0 + 1) * OUTF + col) = o1;
    }
}

// One-wave balanced kernel: 1024 blocks, each exactly 2 groups of 2 rows.
__global__ __launch_bounds__(THREADS, 8)   // regs <= 64
void hermite_fused_kernel(const float* __restrict__ x,
                          const float* __restrict__ coeffs,
                          const float* __restrict__ sigma,
                          float* __restrict__ out)
{
    __shared__ float s_coef[WIDTH * CPAD];       // transposed coeffs [w][o]
    __shared__ float s_partA[NWARPS][WIDTH];
    __shared__ float s_partB[NWARPS][WIDTH];

    const int tid  = threadIdx.x;
    const int lane = tid & 31;
    const int warp = tid >> 5;

    const float s     = fminf(fmaxf(sigma[0], 0.1f), 5.0f);
    const float inv_s = 1.0f / s;
    const float kexp  = -1.4426950408889634f * inv_s * inv_s;

    const int g0 = blockIdx.x;
    const int g1 = blockIdx.x + GRID;            // always < NGROUPS

    const int half = warp & 1;
    const int roff = warp >> 1;                  // row within group (0..1)

    // ---- issue group-0 x loads first ----
    const int row0 = g0 * ROWS_PER_BLOCK + roff;
    const float4* xr =
        reinterpret_cast<const float4*>(x + (size_t)row0 * FEAT)
        + half * (FEAT / 8);
    float4 xv[4];
#pragma unroll
    for (int i = 0; i < 4; ++i) xv[i] = xr[lane + 32 * i];

    // ---- cooperative coeff load -> transposed smem (overlaps x latency) ----
#pragma unroll
    for (int k = 0; k < (OUTF * WIDTH) / THREADS; ++k) {   // 56 iters
        const int idx = tid + k * THREADS;                 // coalesced LDG
        const int o = idx / WIDTH;
        const int w = idx - o * WIDTH;
        s_coef[w * CPAD + o] = coeffs[idx];                // conflict-free STS
    }
    __syncthreads();                              // barrier 1 (coeffs ready)

    float a[WIDTH];
    eval16(xv, inv_s, kexp, a);

    // ---- prefetch group 1's x (latency hides behind reduce + phase2) ----
    float4 xv2[4];
    {
        const int row1 = g1 * ROWS_PER_BLOCK + roff;
        const float4* xr2 =
            reinterpret_cast<const float4*>(x + (size_t)row1 * FEAT)
            + half * (FEAT / 8);
#pragma unroll
        for (int i = 0; i < 4; ++i) xv2[i] = xr2[lane + 32 * i];
    }

    reduce_store(a, s_partA, warp, lane);
    __syncthreads();                              // barrier 2
    phase2(s_partA, s_coef, out, g0, tid);

    // ---- group 1 ----
    float a2[WIDTH];
    eval16(xv2, inv_s, kexp, a2);
    reduce_store(a2, s_partB, warp, lane);
    __syncthreads();                              // barrier 3
    phase2(s_partB, s_coef, out, g1, tid);
}

extern "C" void kernel_launch(void* const* d_in, const int* in_sizes, int n_in,
                              void* d_out, int out_size)
{
    const float* x      = (const float*)d_in[0];   // (4096, 1024)
    const float* coeffs = (const float*)d_in[1];   // (1024, 7)
    const float* sigma  = (const float*)d_in[2];   // (1,)
    float* out          = (float*)d_out;           // (4096, 1024)

    // Max smem carveout so 7 blocks x ~29KB fit per SM (host-side, idempotent,
    // not a stream op -> graph-capture safe).
    cudaFuncSetAttribute(hermite_fused_kernel,
                         cudaFuncAttributePreferredSharedMemoryCarveout,
                         cudaSharedmemCarveoutMaxShared);

    hermite_fused_kernel<<<GRID, THREADS>>>(x, coeffs, sigma, out);
}

// round 12
// speedup vs baseline: 1.1379x; 1.1379x over previous
#include <cuda_runtime.h>

#define DEGREE   6
#define WIDTH    7          // DEGREE - START_DEGREE + 1
#define FEAT     1024       // in_features
#define OUTF     1024       // out_features
#define THREADS  256
#define NWARPS   8
#define ROWS_PER_BLOCK 8    // ONE warp per row, 32 features per lane
#define GRID     512        // 4096/8; single wave (<= 592 resident slots)

__device__ __forceinline__ float ex2f(float x) {
    float r; asm("ex2.approx.f32 %0, %1;" : "=f"(r) : "f"(x)); return r;
}
__device__ __forceinline__ float clipf(float v) {
    return fminf(fmaxf(v, -100.0f), 100.0f);
}

// Warp-per-row kernel with slim phase 2:
//  - each warp reduces one full row (32 feats/lane, 8x front-batched LDG.128)
//  - shuffle-reduce ends with FINAL basis at lane 0 -> two STS.128 (padded)
//  - ONE barrier; phase 2 per thread per row: 2x LDS.128 + 28 FFMA + STG.128
//  - grid 512 = one wave, perfectly balanced, no tail
__global__ __launch_bounds__(THREADS, 4)   // regs <= 64; all 512 blocks resident
void hermite_fused_kernel(const float* __restrict__ x,
                          const float* __restrict__ coeffs,
                          const float* __restrict__ sigma,
                          float* __restrict__ out)
{
    __shared__ float4 s_basis[ROWS_PER_BLOCK][2];   // [row][lo/hi], 7 used + pad

    const int tid  = threadIdx.x;
    const int lane = tid & 31;
    const int warp = tid >> 5;

    const float s     = fminf(fmaxf(sigma[0], 0.1f), 5.0f);
    const float inv_s = 1.0f / s;
    const float kexp  = -1.4426950408889634f * inv_s * inv_s;  // -log2e/s^2

    // ---- Phase 1: whole row per warp (32 features/lane, front-batched) ----
    const int row = blockIdx.x * ROWS_PER_BLOCK + warp;
    const float4* xr = reinterpret_cast<const float4*>(x + (size_t)row * FEAT);

    float4 xv[8];
#pragma unroll
    for (int i = 0; i < 8; ++i) xv[i] = xr[lane + 32 * i];

    float a[WIDTH];
#pragma unroll
    for (int w = 0; w < WIDTH; ++w) a[w] = 0.0f;

#pragma unroll
    for (int i = 0; i < 8; ++i) {
        const float xe[4] = { xv[i].x, xv[i].y, xv[i].z, xv[i].w };
#pragma unroll
        for (int e = 0; e < 4; ++e) {
            const float xq  = xe[e];
            const float txs = xq * (2.0f * inv_s);   // 2*xs = H1
            // g = exp(-xs^2); min(xs^2,50) never binds (delta ~e-50 << tol)
            const float g   = ex2f(xq * xq * kexp);

            a[0] += g;                               // g * H0
            a[1] += g * txs;                         // g * H1

            float hm2 = txs;
            float h   = txs * txs - 2.0f;            // H2: clip can't bind
            a[2] += g * h;                           //  where g > 8e-12
            float hm1 = h;
#pragma unroll
            for (int n = 3; n <= DEGREE; ++n) {
                float t = (-2.0f * (float)(n - 1)) * hm2;  // FMUL-imm
                h = fmaf(txs, hm1, t);
                h = clipf(h);                        // clip BEFORE recursion use
                a[n] += g * h;
                hm2 = hm1;
                hm1 = h;
            }
        }
    }

    // ---- coeff loads (consumed after barrier; latency hides behind reduce) --
    float4 c[7];
    {
        const float4* c4 = reinterpret_cast<const float4*>(
            coeffs + (size_t)(tid * 4) * WIDTH);
#pragma unroll
        for (int i = 0; i < 7; ++i) c[i] = c4[i];
    }
    const float* cf = reinterpret_cast<const float*>(c);

    // ---- warp-local reduction -> FINAL basis at lane 0 ----
#pragma unroll
    for (int w = 0; w < WIDTH; ++w) {
#pragma unroll
        for (int off = 16; off > 0; off >>= 1)
            a[w] += __shfl_xor_sync(0xffffffffu, a[w], off);
    }
    if (lane == 0) {
        s_basis[warp][0] = make_float4(a[0], a[1], a[2], a[3]);
        s_basis[warp][1] = make_float4(a[4], a[5], a[6], 0.0f);
    }

    __syncthreads();   // the ONLY barrier

    // ---- Phase 2: 8 rows x 4 output columns per thread ----
    float* outb = out + (size_t)(blockIdx.x * ROWS_PER_BLOCK) * OUTF;
#pragma unroll
    for (int r = 0; r < ROWS_PER_BLOCK; ++r) {
        const float4 b0 = s_basis[r][0];             // LDS.128 broadcast
        const float4 b1 = s_basis[r][1];             // LDS.128 broadcast
        const float bs[WIDTH] = { b0.x, b0.y, b0.z, b0.w, b1.x, b1.y, b1.z };

        float4 o;
        float* op = reinterpret_cast<float*>(&o);
#pragma unroll
        for (int i = 0; i < 4; ++i) {
            float v = 0.0f;
#pragma unroll
            for (int w = 0; w < WIDTH; ++w)
                v += bs[w] * cf[i * WIDTH + w];
            op[i] = v;
        }
        reinterpret_cast<float4*>(outb + (size_t)r * OUTF)[tid] = o;
    }
}

extern "C" void kernel_launch(void* const* d_in, const int* in_sizes, int n_in,
                              void* d_out, int out_size)
{
    const float* x      = (const float*)d_in[0];   // (4096, 1024)
    const float* coeffs = (const float*)d_in[1];   // (1024, 7)
    const float* sigma  = (const float*)d_in[2];   // (1,)
    float* out          = (float*)d_out;           // (4096, 1024)

    hermite_fused_kernel<<<GRID, THREADS>>>(x, coeffs, sigma, out);
}

// round 13
// speedup vs baseline: 1.1550x; 1.0150x over previous
#include <cuda_runtime.h>

#define DEGREE   6
#define WIDTH    7          // DEGREE - START_DEGREE + 1
#define FEAT     1024       // in_features
#define OUTF     1024       // out_features
#define THREADS  256
#define BATCH    4096
#define GRID     592        // 148 SMs x 4 blocks, ONE wave, uniform 4/SM
#define MAXROWS  7          // ceil(4096/592)

__device__ __forceinline__ float ex2f(float x) {
    float r; asm("ex2.approx.f32 %0, %1;" : "=f"(r) : "f"(x)); return r;
}
__device__ __forceinline__ float clipf(float v) {
    return fminf(fmaxf(v, -100.0f), 100.0f);
}

// Equal-work warp-per-row kernel:
//  - block b owns rows [b*4096/592, (b+1)*4096/592) -> 6 or 7 rows;
//    every SM hosts exactly 4 blocks totalling 27-28 rows (balanced makespan)
//  - warp w (w < len) reduces its whole row: 32 feats/lane, 8x LDG.128,
//    shuffle-reduce, lane 0 stores final basis via 2x STS.128
//  - ONE barrier; phase 2 per thread per row: 2x LDS.128 + 28 FFMA + STG.128
__global__ __launch_bounds__(THREADS, 4)   // regs <= 64; 4 blocks/SM
void hermite_fused_kernel(const float* __restrict__ x,
                          const float* __restrict__ coeffs,
                          const float* __restrict__ sigma,
                          float* __restrict__ out)
{
    __shared__ float4 s_basis[MAXROWS][2];

    const int tid  = threadIdx.x;
    const int lane = tid & 31;
    const int warp = tid >> 5;

    const int start = (blockIdx.x * BATCH) / GRID;
    const int len   = ((blockIdx.x + 1) * BATCH) / GRID - start;  // 6 or 7

    const float s     = fminf(fmaxf(sigma[0], 0.1f), 5.0f);
    const float inv_s = 1.0f / s;
    const float kexp  = -1.4426950408889634f * inv_s * inv_s;  // -log2e/s^2

    // ---- Phase 1: warps 0..len-1 each own one full row ----
    if (warp < len) {
        const int row = start + warp;
        const float4* xr =
            reinterpret_cast<const float4*>(x + (size_t)row * FEAT);

        float4 xv[8];
#pragma unroll
        for (int i = 0; i < 8; ++i) xv[i] = xr[lane + 32 * i];

        float a[WIDTH];
#pragma unroll
        for (int w = 0; w < WIDTH; ++w) a[w] = 0.0f;

#pragma unroll
        for (int i = 0; i < 8; ++i) {
            const float xe[4] = { xv[i].x, xv[i].y, xv[i].z, xv[i].w };
#pragma unroll
            for (int e = 0; e < 4; ++e) {
                const float xq  = xe[e];
                const float txs = xq * (2.0f * inv_s);   // 2*xs = H1
                // g = exp(-xs^2); min(xs^2,50) never binds (delta ~e-50)
                const float g   = ex2f(xq * xq * kexp);

                a[0] += g;                               // g * H0
                a[1] += g * txs;                         // g * H1

                float hm2 = txs;
                float h   = txs * txs - 2.0f;            // H2: clip can't bind
                a[2] += g * h;                           //  where g > 8e-12
                float hm1 = h;
#pragma unroll
                for (int n = 3; n <= DEGREE; ++n) {
                    float t = (-2.0f * (float)(n - 1)) * hm2;  // FMUL-imm
                    h = fmaf(txs, hm1, t);
                    h = clipf(h);                  // clip BEFORE recursion use
                    a[n] += g * h;
                    hm2 = hm1;
                    hm1 = h;
                }
            }
        }

        // warp-local reduction -> FINAL basis at lane 0
#pragma unroll
        for (int w = 0; w < WIDTH; ++w) {
#pragma unroll
            for (int off = 16; off > 0; off >>= 1)
                a[w] += __shfl_xor_sync(0xffffffffu, a[w], off);
        }
        if (lane == 0) {
            s_basis[warp][0] = make_float4(a[0], a[1], a[2], a[3]);
            s_basis[warp][1] = make_float4(a[4], a[5], a[6], 0.0f);
        }
    }

    // ---- coeff loads (all threads; consumed after the barrier) ----
    float4 c[7];
    {
        const float4* c4 = reinterpret_cast<const float4*>(
            coeffs + (size_t)(tid * 4) * WIDTH);
#pragma unroll
        for (int i = 0; i < 7; ++i) c[i] = c4[i];
    }
    const float* cf = reinterpret_cast<const float*>(c);

    __syncthreads();   // the ONLY barrier

    // ---- Phase 2: len rows x 4 output columns per thread ----
    float* outb = out + (size_t)start * OUTF;
#pragma unroll
    for (int r = 0; r < MAXROWS; ++r) {
        if (r < len) {
            const float4 b0 = s_basis[r][0];         // LDS.128 broadcast
            const float4 b1 = s_basis[r][1];         // LDS.128 broadcast
            const float bs[WIDTH] =
                { b0.x, b0.y, b0.z, b0.w, b1.x, b1.y, b1.z };

            float4 o;
            float* op = reinterpret_cast<float*>(&o);
#pragma unroll
            for (int i = 0; i < 4; ++i) {
                float v = 0.0f;
#pragma unroll
                for (int w = 0; w < WIDTH; ++w)
                    v += bs[w] * cf[i * WIDTH + w];
                op[i] = v;
            }
            reinterpret_cast<float4*>(outb + (size_t)r * OUTF)[tid] = o;
        }
    }
}

extern "C" void kernel_launch(void* const* d_in, const int* in_sizes, int n_in,
                              void* d_out, int out_size)
{
    const float* x      = (const float*)d_in[0];   // (4096, 1024)
    const float* coeffs = (const float*)d_in[1];   // (1024, 7)
    const float* sigma  = (const float*)d_in[2];   // (1,)
    float* out          = (float*)d_out;           // (4096, 1024)

    hermite_fused_kernel<<<GRID, THREADS>>>(x, coeffs, sigma, out);
}